// round 11
// baseline (speedup 1.0000x reference)
#include <cuda_runtime.h>

#define N_CELLS 776
#define N_ANCHORS 3
#define N_CH 7
#define CONF_THRESH 0.8f
#define NO_OBJECT 0.5f
#define BLOCK 1024

__global__ __launch_bounds__(BLOCK, 1)
void yolo_loss_kernel(const float* __restrict__ pred,
                      const float* __restrict__ label,
                      float* __restrict__ out)
{
    __shared__ float warp_sums[BLOCK / 32];

    const int tid = threadIdx.x;

    float loss = 0.0f;
    if (tid < N_CELLS) {
        const float* row = pred + (size_t)tid * (N_ANCHORS * N_CH);

        // Load ALL 21 channels up front: independent loads, one latency
        // exposure (MLP=21), no address-dependent second fetch.
        float ch[N_ANCHORS][N_CH];
        #pragma unroll
        for (int a = 0; a < N_ANCHORS; a++)
            #pragma unroll
            for (int k = 0; k < N_CH; k++)
                ch[a][k] = __ldg(&row[a * N_CH + k]);

        // Label broadcast (uniform address, L2-hit after first warp)
        const float lx = __ldg(&label[0]);
        const float ly = __ldg(&label[1]);
        const float lw = __ldg(&label[2]);
        const float lh = __ldg(&label[3]);
        const float lconf = __ldg(&label[4]);
        const float lc5 = __ldg(&label[5]);
        const float lc6 = __ldg(&label[6]);

        const float area_b = fabsf(lw * lh);
        const float lxm = lx - lw * 0.5f, lym = ly - lh * 0.5f;
        const float lxp = lx + lw * 0.5f, lyp = ly + lh * 0.5f;

        // argmax of IoU over anchors; select best anchor's channels via
        // register predication (first-max tie-break: strict >)
        float best_iou = -1.0f;
        float b0 = 0.f, b1 = 0.f, b4 = 0.f, b5 = 0.f, b6 = 0.f;
        #pragma unroll
        for (int a = 0; a < N_ANCHORS; a++) {
            const float px = ch[a][0], py = ch[a][1];
            const float pw = ch[a][2], ph = ch[a][3];
            const float ax = fmaxf(px - pw * 0.5f, lxm);
            const float ay = fmaxf(py - ph * 0.5f, lym);
            const float bx = fminf(px + pw * 0.5f, lxp);
            const float by = fminf(py + ph * 0.5f, lyp);
            const float inter = fabsf(fmaxf(bx - ax, 0.0f) * fmaxf(by - ay, 0.0f));
            const float area_a = fabsf(pw * ph);
            const float iou = inter / (area_a + area_b - inter);
            const bool take = iou > best_iou;
            best_iou = take ? iou : best_iou;
            b0 = take ? px : b0;
            b1 = take ? py : b1;
            b4 = take ? ch[a][4] : b4;
            b5 = take ? ch[a][5] : b5;
            b6 = take ? ch[a][6] : b6;
        }

        const float dx = lx - b0, dy = ly - b1;
        const float xy_loss = dx * dx + dy * dy;
        const float sdx = sqrtf(lx) - sqrtf(b0);
        const float sdy = sqrtf(ly) - sqrtf(b1);
        const float wh_loss = sdx * sdx + sdy * sdy;

        const bool has_obj = b4 > CONF_THRESH;
        float class_loss = 0.0f;
        if (has_obj) {
            const float d5 = lc5 - b5, d6 = lc6 - b6;
            class_loss = d5 * d5 + d6 * d6;
        }
        const float dc = lconf - b4;
        const float conf_sq = dc * dc;
        const float conf_loss = has_obj ? conf_sq : NO_OBJECT * conf_sq;

        loss = xy_loss + wh_loss + class_loss + conf_loss;
    }

    // Shuffle-first reduction: one barrier total.
    #pragma unroll
    for (int off = 16; off > 0; off >>= 1)
        loss += __shfl_down_sync(0xFFFFFFFF, loss, off);
    if ((tid & 31) == 0) warp_sums[tid >> 5] = loss;
    __syncthreads();

    if (tid < 32) {
        float v = warp_sums[tid];
        #pragma unroll
        for (int off = 16; off > 0; off >>= 1)
            v += __shfl_down_sync(0xFFFFFFFF, v, off);
        if (tid == 0) out[0] = v;
    }
}

extern "C" void kernel_launch(void* const* d_in, const int* in_sizes, int n_in,
                              void* d_out, int out_size)
{
    const float* pred  = (const float*)d_in[0];
    const float* label = (const float*)d_in[1];
    float* out = (float*)d_out;
    yolo_loss_kernel<<<1, BLOCK>>>(pred, label, out);
}